// round 5
// baseline (speedup 1.0000x reference)
#include <cuda_runtime.h>
#include <cstdint>

#define N      2048
#define DIN    256
#define PROJC  256
#define PTM    8           // proj kernel row tile
#define TM     8           // attn rows per CTA
#define NW     8           // warps per attn CTA
#define STAGES 4
#define NIT    (N / NW)    // 256 iterations, j = w + 8k

// 2 MB scratch for projection output: cols = [Q(64) | K(64) | V(64) | R(64)]
__device__ float g_proj[N * PROJC];

// ---------------------------------------------------------------------------
// Kernel 1: proj = H @ W^T
// ---------------------------------------------------------------------------
__global__ __launch_bounds__(256) void proj_kernel(const float* __restrict__ H,
                                                   const float* __restrict__ W,
                                                   float* __restrict__ proj) {
    __shared__ float Hsh[PTM][64];
    extern __shared__ float Wsh[];          // [256][65]
    const int t  = threadIdx.x;
    const int i0 = blockIdx.x * PTM;

    float acc[PTM];
#pragma unroll
    for (int i = 0; i < PTM; i++) acc[i] = 0.f;

    for (int kc = 0; kc < DIN; kc += 64) {
        if (t < PTM * 64 / 4) {
#pragma unroll
            for (int r = 0; r < 4; r++) {
                int idx = t + r * 128;
                if (idx < PTM * 64)
                    Hsh[idx >> 6][idx & 63] = H[(i0 + (idx >> 6)) * DIN + kc + (idx & 63)];
            }
        }
#pragma unroll 8
        for (int r = 0; r < 64; r++) {
            int idx = t + r * 256;
            Wsh[(idx >> 6) * 65 + (idx & 63)] = W[(idx >> 6) * DIN + kc + (idx & 63)];
        }
        __syncthreads();
#pragma unroll
        for (int k = 0; k < 64; k++) {
            float w = Wsh[t * 65 + k];
#pragma unroll
            for (int i = 0; i < PTM; i++) acc[i] = fmaf(Hsh[i][k], w, acc[i]);
        }
        __syncthreads();
    }
#pragma unroll
    for (int i = 0; i < PTM; i++) proj[(i0 + i) * PROJC + t] = acc[i];
}

// ---------------------------------------------------------------------------
__device__ __forceinline__ float combine2(float a, float b, int mask, int l) {
    float sel = (l & mask) ? a : b;
    float t = __shfl_xor_sync(0xffffffffu, sel, mask);
    return (l & mask) ? (b + t) : (a + t);
}

__device__ __forceinline__ void cp16(uint32_t s, const void* g) {
    asm volatile("cp.async.cg.shared.global [%0], [%1], 16;\n" :: "r"(s), "l"(g));
}

__device__ __forceinline__ float ex2(float x) {
    float y;
    asm("ex2.approx.ftz.f32 %0, %1;" : "=f"(y) : "f"(x));
    return y;
}

// ---------------------------------------------------------------------------
// Kernel 2: fused scores + max-free online softmax (base-2) + P@V.
// 8 warps / 256 threads, 2 CTAs/SM. Warp w streams D[i0..i0+7, j=w+8k, :]
// through a private 4-stage ring. Lane split: h = l>>4 selects row parity,
// m = l&15 owns dims 4m..4m+3. Pass p handles row 2p+h.
// ---------------------------------------------------------------------------
__global__ __launch_bounds__(256, 2) void attn_kernel(const float* __restrict__ D,
                                                      const float* __restrict__ proj,
                                                      float* __restrict__ out) {
    extern __shared__ float smem[];
    const int t  = threadIdx.x;
    const int w  = t >> 5;
    const int l  = t & 31;
    const int m  = l & 15;
    const int h  = l >> 4;
    const int i0 = blockIdx.x * TM;

    float* wbuf    = smem + w * (STAGES * 512);            // 4 stages x 2KB
    float* scratch = smem + NW * STAGES * 512 + w * 8;     // 8 scores per warp
    const uint32_t wbuf_s = (uint32_t)__cvta_generic_to_shared(wbuf);

    // scale * log2(e): softmax done in base 2.
    const float SCL = 0.08838834764831845f * 1.4426950408889634f;

    // Pre-scaled Q,R fragments: qp[p]/rp[p] = row (i0+2p+h), dims 4m..4m+3.
    float4 qp[4], rp[4];
#pragma unroll
    for (int p = 0; p < 4; p++) {
        const float* row = proj + (size_t)(i0 + 2 * p + h) * PROJC;
        float4 qq = *(const float4*)(row + 4 * m);
        float4 rr = *(const float4*)(row + 192 + 4 * m);
        qp[p] = make_float4(qq.x * SCL, qq.y * SCL, qq.z * SCL, qq.w * SCL);
        rp[p] = make_float4(rr.x * SCL, rr.y * SCL, rr.z * SCL, rr.w * SCL);
    }

    // Prologue: fill all 4 stages. Stage = 8 rows x 256B; lane copies
    // 4 x 16B chunks: flat idx = l + 32c -> row = idx>>4, u = idx&15.
    uint32_t soff[4];
    const float* gp[4];
#pragma unroll
    for (int c = 0; c < 4; c++) {
        int idx = l + 32 * c;
        soff[c] = (uint32_t)(idx * 16);
        gp[c]   = D + (((size_t)(i0 + (idx >> 4)) * N + (w + NW * STAGES)) << 6) + ((idx & 15) << 2);
    }
#pragma unroll
    for (int s = 0; s < STAGES; s++) {
        int j = w + NW * s;
#pragma unroll
        for (int c = 0; c < 4; c++) {
            int idx = l + 32 * c;
            const float* g = D + (((size_t)(i0 + (idx >> 4)) * N + j) << 6) + ((idx & 15) << 2);
            cp16(wbuf_s + (uint32_t)(s * 2048) + soff[c], g);
        }
        asm volatile("cp.async.commit_group;\n" ::: "memory");
    }

    // Prefetch K/V for j = w (dims 4m..4m+3, replicated across halves).
    float4 kv = *(const float4*)(proj + (size_t)w * PROJC + 64 + 4 * m);
    float4 vv = *(const float4*)(proj + (size_t)w * PROJC + 128 + 4 * m);

    // Packed-tree result index for this lane (which of the 4 rows it ends with).
    const int idxr = ((m >> 3) & 1) | (((m >> 2) & 1) << 1);

    float  sum[4];
    float4 acc[4];
#pragma unroll
    for (int p = 0; p < 4; p++) { sum[p] = 0.f; acc[p] = make_float4(0.f, 0.f, 0.f, 0.f); }

    for (int k = 0; k < NIT; k++) {
        asm volatile("cp.async.wait_group 3;\n" ::: "memory");
        __syncwarp();

        const float* Db = wbuf + (k & 3) * 512;
        float v[4];
#pragma unroll
        for (int p = 0; p < 4; p++) {
            float4 dv = *(const float4*)(Db + (2 * p + h) * 64 + 4 * m);
            float qk = fmaf(kv.x, qp[p].x, fmaf(kv.y, qp[p].y,
                       fmaf(kv.z, qp[p].z, kv.w * qp[p].w)));
            v[p] = fmaf(dv.x, rp[p].x, fmaf(dv.y, rp[p].y,
                   fmaf(dv.z, rp[p].z, fmaf(dv.w, rp[p].w, qk))));
        }
        // 8 simultaneous 16-lane reductions (both halves) in 5 shfls.
        float c0 = combine2(v[0], v[1], 8, l);
        float c1 = combine2(v[2], v[3], 8, l);
        float d0 = combine2(c0, c1, 4, l);
        float e0 = d0 + __shfl_xor_sync(0xffffffffu, d0, 2);
        float f0 = e0 + __shfl_xor_sync(0xffffffffu, e0, 1);
        if ((m & 3) == 0) scratch[h * 4 + idxr] = f0;   // row 2*idxr+h
        __syncwarp();

        // Refill the stage we just consumed (j = w + 8*(k+4)).
        if (k + STAGES < NIT) {
#pragma unroll
            for (int c = 0; c < 4; c++)
                cp16(wbuf_s + (uint32_t)((k & 3) * 2048) + soff[c], gp[c]);
        }
#pragma unroll
        for (int c = 0; c < 4; c++) gp[c] += NW * 64;
        asm volatile("cp.async.commit_group;\n" ::: "memory");

        // Probs for this lane's 4 rows + prefetch next K/V.
        float4 pr = *(const float4*)(scratch + h * 4);   // rows {h,2+h,4+h,6+h}
        int jn = (w + NW * (k + 1)) & (N - 1);
        float4 kn = *(const float4*)(proj + (size_t)jn * PROJC + 64 + 4 * m);
        float4 vn = *(const float4*)(proj + (size_t)jn * PROJC + 128 + 4 * m);

        float p0 = ex2(pr.x), p1 = ex2(pr.y), p2 = ex2(pr.z), p3 = ex2(pr.w);
        sum[0] += p0; sum[1] += p1; sum[2] += p2; sum[3] += p3;
        acc[0].x = fmaf(p0, vv.x, acc[0].x); acc[0].y = fmaf(p0, vv.y, acc[0].y);
        acc[0].z = fmaf(p0, vv.z, acc[0].z); acc[0].w = fmaf(p0, vv.w, acc[0].w);
        acc[1].x = fmaf(p1, vv.x, acc[1].x); acc[1].y = fmaf(p1, vv.y, acc[1].y);
        acc[1].z = fmaf(p1, vv.z, acc[1].z); acc[1].w = fmaf(p1, vv.w, acc[1].w);
        acc[2].x = fmaf(p2, vv.x, acc[2].x); acc[2].y = fmaf(p2, vv.y, acc[2].y);
        acc[2].z = fmaf(p2, vv.z, acc[2].z); acc[2].w = fmaf(p2, vv.w, acc[2].w);
        acc[3].x = fmaf(p3, vv.x, acc[3].x); acc[3].y = fmaf(p3, vv.y, acc[3].y);
        acc[3].z = fmaf(p3, vv.z, acc[3].z); acc[3].w = fmaf(p3, vv.w, acc[3].w);

        kv = kn; vv = vn;
    }

    asm volatile("cp.async.wait_group 0;\n" ::: "memory");

    // ---------------- epilogue: combine the 8 warps' partials ----------------
    __syncthreads();
    float* accsh = smem;                   // [8 warps][8 rows][64]
    float* sumsh = smem + NW * TM * 64;    // [8 warps][8 rows]
#pragma unroll
    for (int p = 0; p < 4; p++)
        *(float4*)(accsh + ((w * TM + 2 * p + h) * 64) + 4 * m) = acc[p];
    if (m == 0) {
#pragma unroll
        for (int p = 0; p < 4; p++) sumsh[w * TM + 2 * p + h] = sum[p];
    }
    __syncthreads();
    {
        float2 tot = make_float2(0.f, 0.f);
        float  st  = 0.f;
#pragma unroll
        for (int ww = 0; ww < NW; ww++) {
            float2 a = *(const float2*)(accsh + ((ww * TM + w) * 64) + 2 * l);
            tot.x += a.x; tot.y += a.y;
            st += sumsh[ww * TM + w];
        }
        float inv = 1.0f / st;
        *(float2*)(out + (size_t)(i0 + w) * 64 + 2 * l) = make_float2(tot.x * inv, tot.y * inv);
    }
}

// ---------------------------------------------------------------------------
extern "C" void kernel_launch(void* const* d_in, const int* in_sizes, int n_in,
                              void* d_out, int out_size) {
    const float* H = (const float*)d_in[0];
    const float* D = (const float*)d_in[1];
    const float* W = (const float*)d_in[2];
    float* out = (float*)d_out;

    const int proj_smem = 256 * 65 * 4;                               // 66,560 B
    const int attn_smem = (NW * STAGES * 512 + NW * 8) * 4;           // 65,792 B
    cudaFuncSetAttribute(proj_kernel, cudaFuncAttributeMaxDynamicSharedMemorySize, proj_smem);
    cudaFuncSetAttribute(attn_kernel, cudaFuncAttributeMaxDynamicSharedMemorySize, attn_smem);

    void* proj_ptr = nullptr;
    cudaGetSymbolAddress(&proj_ptr, g_proj);
    float* proj = (float*)proj_ptr;

    proj_kernel<<<N / PTM, 256, proj_smem>>>(H, W, proj);
    attn_kernel<<<N / TM, 256, attn_smem>>>(D, proj, out);
}